// round 6
// baseline (speedup 1.0000x reference)
#include <cuda_runtime.h>
#include <math.h>

#define NN 4096
#define FIN 128
#define FOUT 64
#define NHEADS 4
#define HF 256
#define NEG_INF_F (-1e9f)

// ---------------- device scratch ----------------
__device__ float g_mask[NN * NN];                  // 64MB raw mask
__device__ float g_proj[NHEADS * NN * FOUT];       // [h][n][o]
__device__ float g_skip[NN * HF];                  // [n][h*64+o]
__device__ float g_ssrc[NHEADS * NN];
__device__ float g_stgt[NHEADS * NN];
__device__ float g_rowsum[NN];
__device__ float g_rowsq[NN];
__device__ float g_colsum[NHEADS * NN];
__device__ float g_part[4 * NHEADS * NN * FOUT];   // 16.8MB partials (4 j-splits)

// ---------------- packed f32x2 helpers ----------------
__device__ __forceinline__ unsigned long long ffma2(unsigned long long a,
                                                    unsigned long long b,
                                                    unsigned long long c) {
    unsigned long long d;
    asm("fma.rn.f32x2 %0, %1, %2, %3;" : "=l"(d) : "l"(a), "l"(b), "l"(c));
    return d;
}
__device__ __forceinline__ float2 unpk(unsigned long long v) {
    unsigned int lo, hi;
    asm("mov.b64 {%0, %1}, %2;" : "=r"(lo), "=r"(hi) : "l"(v));
    return make_float2(__uint_as_float(lo), __uint_as_float(hi));
}

// ---- launch 0: kP2 — nodes[4096x128] @ [proj|skip] -> g_proj, g_skip -------
__global__ __launch_bounds__(256) void kP2(const float* __restrict__ nodes,
                                           const float* __restrict__ pp,
                                           const float* __restrict__ sw) {
    __shared__ float a_s[64 * FIN];   // 32KB
    int t = threadIdx.x;
    int n0 = blockIdx.y * 64;
    int isw = blockIdx.x;             // 0 = proj, 1 = skip
#pragma unroll
    for (int r = 0; r < 32; r++)
        a_s[r * 256 + t] = nodes[n0 * FIN + r * 256 + t];
    __syncthreads();

    float acc[64];
#pragma unroll
    for (int n = 0; n < 64; n++) acc[n] = 0.f;

    if (isw == 0) {
        int h = t >> 6, o = t & 63;
        const float* wcol = pp + h * (FIN * FOUT) + o;
        for (int k4 = 0; k4 < 32; k4++) {
            float w0 = __ldg(&wcol[(4 * k4 + 0) * FOUT]);
            float w1 = __ldg(&wcol[(4 * k4 + 1) * FOUT]);
            float w2 = __ldg(&wcol[(4 * k4 + 2) * FOUT]);
            float w3 = __ldg(&wcol[(4 * k4 + 3) * FOUT]);
#pragma unroll
            for (int n = 0; n < 64; n++) {
                float4 a = *(const float4*)&a_s[n * FIN + 4 * k4];
                acc[n] = fmaf(a.x, w0, acc[n]);
                acc[n] = fmaf(a.y, w1, acc[n]);
                acc[n] = fmaf(a.z, w2, acc[n]);
                acc[n] = fmaf(a.w, w3, acc[n]);
            }
        }
        for (int n = 0; n < 64; n++)
            g_proj[(h * NN + n0 + n) * FOUT + o] = acc[n];
    } else {
        const float* wcol = sw + t * FIN;
        for (int k4 = 0; k4 < 32; k4++) {
            float4 w = __ldg((const float4*)&wcol[4 * k4]);
#pragma unroll
            for (int n = 0; n < 64; n++) {
                float4 a = *(const float4*)&a_s[n * FIN + 4 * k4];
                acc[n] = fmaf(a.x, w.x, acc[n]);
                acc[n] = fmaf(a.y, w.y, acc[n]);
                acc[n] = fmaf(a.z, w.z, acc[n]);
                acc[n] = fmaf(a.w, w.w, acc[n]);
            }
        }
        for (int n = 0; n < 64; n++)
            g_skip[(n0 + n) * HF + t] = acc[n];
    }
}

// ---- launch 1: kSZ — per-node per-head scalar scores + zero accumulators ---
__global__ void kSZ(const float* __restrict__ ssv, const float* __restrict__ stv) {
    int id = blockIdx.x * 256 + threadIdx.x;   // 16384
    g_colsum[id] = 0.f;
    if (id < NN) { g_rowsum[id] = 0.f; g_rowsq[id] = 0.f; }
    int h = id >> 12, n = id & 4095;
    const float4* pr = (const float4*)&g_proj[(h * NN + n) * FOUT];
    const float4* a = (const float4*)(ssv + h * FOUT);
    const float4* b = (const float4*)(stv + h * FOUT);
    float s1 = 0.f, s2 = 0.f;
#pragma unroll
    for (int q = 0; q < 16; q++) {
        float4 p = pr[q];
        float4 av = __ldg(&a[q]);
        float4 bv = __ldg(&b[q]);
        s1 += p.x * av.x + p.y * av.y + p.z * av.z + p.w * av.w;
        s2 += p.x * bv.x + p.y * bv.y + p.z * bv.z + p.w * bv.w;
    }
    g_ssrc[id] = s1;
    g_stgt[id] = s2;
}

// ---- launch 2: kM — mask + row stats + column exp-sums ----
__global__ __launch_bounds__(256) void kM(const float* __restrict__ deg,
                                          const float* __restrict__ bond,
                                          const int* __restrict__ cutp) {
    __shared__ float cs[NHEADS][128];
    int t = threadIdx.x;
    int col = t & 127, half = t >> 7;
    int j0 = blockIdx.x * 128, i0 = blockIdx.y * 128;
    float cut = (float)__ldg(cutp);
    float st[NHEADS], acc[NHEADS];
#pragma unroll
    for (int h = 0; h < NHEADS; h++) {
        st[h] = __ldg(&g_stgt[h * NN + j0 + col]);
        acc[h] = 0.f;
    }
    for (int s = 0; s < 64; s++) {
        int gi = i0 + 2 * s + half;
        int g = gi * NN + j0 + col;
        float d = deg[g], b = bond[g];
        float wdm = d + b;
        float m = (wdm > 0.f) ? wdm : ((b > cut) ? (b + wdm) : NEG_INF_F);
        g_mask[g] = m;
        float s1 = m, s2 = m * m;
#pragma unroll
        for (int off = 16; off; off >>= 1) {
            s1 += __shfl_down_sync(0xffffffffu, s1, off);
            s2 += __shfl_down_sync(0xffffffffu, s2, off);
        }
        if ((t & 31) == 0) {
            atomicAdd(&g_rowsum[gi], s1);
            atomicAdd(&g_rowsq[gi], s2);
        }
#pragma unroll
        for (int h = 0; h < NHEADS; h++) {
            float x = __ldg(&g_ssrc[h * NN + gi]) + st[h];
            float lr = fmaxf(x, 0.2f * x);
            acc[h] += __expf(lr + m);
        }
    }
    if (half == 1) {
#pragma unroll
        for (int h = 0; h < NHEADS; h++) cs[h][col] = acc[h];
    }
    __syncthreads();
    if (half == 0) {
#pragma unroll
        for (int h = 0; h < NHEADS; h++)
            atomicAdd(&g_colsum[h * NN + j0 + col], acc[h] + cs[h][col]);
    }
}

// ---- launch 3: kA4 — fused attn-gen + GEMM + mask_ln ------
// grid (4h, 32it, 4js) = 512 CTAs of 128 threads (4 CTAs/SM).
// Tile: 128 i x 64 f x 1024 j. at holds PRE-DUPLICATED pairs (a,a) so the
// GEMM loads the FFMA2 operand directly with LDS.64 (no dup MOVs).
#define ATP2 66   // at pitch in floats: 32 j-pairs * 2 + 2 pad
#define PRP 68
__global__ __launch_bounds__(128, 4) void kA4(float* __restrict__ lnp) {
    __shared__ float at[128 * ATP2];   // 33.8KB
    __shared__ float pr[32 * PRP];     // 8.7KB
    __shared__ float sss[128], smu[128], sis[128];
    int t = threadIdx.x;
    int h = blockIdx.x;
    int i0 = blockIdx.y * 128;
    int jbase = blockIdx.z * 1024;
    bool do_ln = (h == 0);

    // cache ssrc for this i-tile; inline row stats (for mask_ln)
    sss[t] = __ldg(&g_ssrc[h * NN + i0 + t]);
    if (do_ln) {
        float mu = g_rowsum[i0 + t] * (1.0f / NN);
        float var = fmaxf(g_rowsq[i0 + t] * (1.0f / NN) - mu * mu, 0.f);
        smu[t] = mu;
        sis[t] = rsqrtf(var + 1e-5f);
    }
    __syncthreads();

    // fill-phase indices: warp w handles i-rows w*32..w*32+31? No:
    // jf = lane (32 j), ig = warp (4 groups of 32 i rows)
    int jf = t & 31, ig = t >> 5;
    // gemm-phase indices
    int tx = t & 7, ty = t >> 3;           // tx 0..7 (f), ty 0..15 (i)
    int f0 = 4 * tx, iA = 4 * ty;
    // pr fill indices
    int prw = t >> 3, pf = (t & 7) * 8;    // rows prw and prw+16

    unsigned long long acc[8][4];
#pragma unroll
    for (int r = 0; r < 8; r++)
#pragma unroll
        for (int c = 0; c < 4; c++) acc[r][c] = 0ull;

    const float* stb = g_stgt + h * NN;

    for (int jt = 0; jt < 32; jt++) {
        int j0 = jbase + jt * 32;
        // pr fill: pr[j][f] = proj[j][f] / colsum[j]  (2 rows per thread)
#pragma unroll
        for (int rr = 0; rr < 2; rr++) {
            int row = prw + rr * 16;
            float cvv = __fdividef(1.0f, __ldg(&g_colsum[h * NN + j0 + row]));
            const float4* src =
                (const float4*)&g_proj[(h * NN + j0 + row) * FOUT + pf];
            float4 v0 = src[0], v1 = src[1];
            v0.x *= cvv; v0.y *= cvv; v0.z *= cvv; v0.w *= cvv;
            v1.x *= cvv; v1.y *= cvv; v1.z *= cvv; v1.w *= cvv;
            *(float4*)&pr[row * PRP + pf] = v0;
            *(float4*)&pr[row * PRP + pf + 4] = v1;
        }
        // at fill: duplicated pairs (a,a); + mask_ln for h==0
        float stv = __ldg(&stb[j0 + jf]);
#pragma unroll 4
        for (int r = 0; r < 32; r++) {
            int i = ig * 32 + r;
            int gi = i0 + i;
            float m = g_mask[gi * NN + j0 + jf];
            float x = sss[i] + stv;
            float lr = fmaxf(x, 0.2f * x);
            float a = __expf(lr + m);
            *(float2*)&at[i * ATP2 + 2 * jf] = make_float2(a, a);
            if (do_ln)
                lnp[gi * NN + j0 + jf] = (m - smu[i]) * sis[i];
        }
        __syncthreads();
        // GEMM: 8i x 8f per thread; a operands loaded pre-duplicated (LDS.64)
#pragma unroll 8
        for (int kk = 0; kk < 32; kk++) {
            const float* ab = at + 2 * kk;
            unsigned long long a0 = *(const unsigned long long*)&ab[(iA + 0) * ATP2];
            unsigned long long a1 = *(const unsigned long long*)&ab[(iA + 1) * ATP2];
            unsigned long long a2 = *(const unsigned long long*)&ab[(iA + 2) * ATP2];
            unsigned long long a3 = *(const unsigned long long*)&ab[(iA + 3) * ATP2];
            unsigned long long a4 = *(const unsigned long long*)&ab[(iA + 64) * ATP2];
            unsigned long long a5 = *(const unsigned long long*)&ab[(iA + 65) * ATP2];
            unsigned long long a6 = *(const unsigned long long*)&ab[(iA + 66) * ATP2];
            unsigned long long a7 = *(const unsigned long long*)&ab[(iA + 67) * ATP2];
            ulonglong2 bL = *(const ulonglong2*)&pr[kk * PRP + f0];
            ulonglong2 bH = *(const ulonglong2*)&pr[kk * PRP + f0 + 32];
            acc[0][0] = ffma2(a0, bL.x, acc[0][0]); acc[0][1] = ffma2(a0, bL.y, acc[0][1]);
            acc[0][2] = ffma2(a0, bH.x, acc[0][2]); acc[0][3] = ffma2(a0, bH.y, acc[0][3]);
            acc[1][0] = ffma2(a1, bL.x, acc[1][0]); acc[1][1] = ffma2(a1, bL.y, acc[1][1]);
            acc[1][2] = ffma2(a1, bH.x, acc[1][2]); acc[1][3] = ffma2(a1, bH.y, acc[1][3]);
            acc[2][0] = ffma2(a2, bL.x, acc[2][0]); acc[2][1] = ffma2(a2, bL.y, acc[2][1]);
            acc[2][2] = ffma2(a2, bH.x, acc[2][2]); acc[2][3] = ffma2(a2, bH.y, acc[2][3]);
            acc[3][0] = ffma2(a3, bL.x, acc[3][0]); acc[3][1] = ffma2(a3, bL.y, acc[3][1]);
            acc[3][2] = ffma2(a3, bH.x, acc[3][2]); acc[3][3] = ffma2(a3, bH.y, acc[3][3]);
            acc[4][0] = ffma2(a4, bL.x, acc[4][0]); acc[4][1] = ffma2(a4, bL.y, acc[4][1]);
            acc[4][2] = ffma2(a4, bH.x, acc[4][2]); acc[4][3] = ffma2(a4, bH.y, acc[4][3]);
            acc[5][0] = ffma2(a5, bL.x, acc[5][0]); acc[5][1] = ffma2(a5, bL.y, acc[5][1]);
            acc[5][2] = ffma2(a5, bH.x, acc[5][2]); acc[5][3] = ffma2(a5, bH.y, acc[5][3]);
            acc[6][0] = ffma2(a6, bL.x, acc[6][0]); acc[6][1] = ffma2(a6, bL.y, acc[6][1]);
            acc[6][2] = ffma2(a6, bH.x, acc[6][2]); acc[6][3] = ffma2(a6, bH.y, acc[6][3]);
            acc[7][0] = ffma2(a7, bL.x, acc[7][0]); acc[7][1] = ffma2(a7, bL.y, acc[7][1]);
            acc[7][2] = ffma2(a7, bH.x, acc[7][2]); acc[7][3] = ffma2(a7, bH.y, acc[7][3]);
        }
        __syncthreads();
    }
    // store partials: rows iA+0..3 and iA+64..67
    float* pbase = g_part + ((size_t)(blockIdx.z * NHEADS + h)) * (NN * FOUT);
#pragma unroll
    for (int r = 0; r < 8; r++) {
        int gi = i0 + iA + (r < 4 ? r : 60 + r);
        float2 lo0 = unpk(acc[r][0]);
        float2 hi0 = unpk(acc[r][1]);
        float2 lo1 = unpk(acc[r][2]);
        float2 hi1 = unpk(acc[r][3]);
        *(float4*)&pbase[gi * FOUT + f0] = make_float4(lo0.x, lo0.y, hi0.x, hi0.y);
        *(float4*)&pbase[gi * FOUT + f0 + 32] = make_float4(lo1.x, lo1.y, hi1.x, hi1.y);
    }
}

// ---- launch 4: kC — combine 4 partials + skip + ELU ----
__global__ void kC(float* __restrict__ outp) {
    int id = blockIdx.x * 256 + threadIdx.x;   // 0 .. 262143
    int nf = id * 4;
    int n = nf >> 8;
    int c = nf & 255;
    int h = c >> 6, f = c & 63;
    size_t base = ((size_t)h * NN + n) * FOUT + f;
    const size_t stride = (size_t)NHEADS * NN * FOUT;
    float4 p0 = *(const float4*)&g_part[base];
    float4 p1 = *(const float4*)&g_part[base + stride];
    float4 p2 = *(const float4*)&g_part[base + 2 * stride];
    float4 p3 = *(const float4*)&g_part[base + 3 * stride];
    float4 sk = *(const float4*)&g_skip[n * HF + c];
    float v0 = (p0.x + p1.x) + (p2.x + p3.x) + sk.x;
    float v1 = (p0.y + p1.y) + (p2.y + p3.y) + sk.y;
    float v2 = (p0.z + p1.z) + (p2.z + p3.z) + sk.z;
    float v3 = (p0.w + p1.w) + (p2.w + p3.w) + sk.w;
    v0 = v0 > 0.f ? v0 : expm1f(v0);
    v1 = v1 > 0.f ? v1 : expm1f(v1);
    v2 = v2 > 0.f ? v2 : expm1f(v2);
    v3 = v3 > 0.f ? v3 : expm1f(v3);
    *(float4*)&outp[nf] = make_float4(v0, v1, v2, v3);
}

// ---------------- host launch ----------------
extern "C" void kernel_launch(void* const* d_in, const int* in_sizes, int n_in,
                              void* d_out, int out_size) {
    const float* nodes = (const float*)d_in[0];
    const float* deg   = (const float*)d_in[1];
    const float* bond  = (const float*)d_in[3];
    const float* pp    = (const float*)d_in[4];
    const float* ssv   = (const float*)d_in[5];
    const float* stv   = (const float*)d_in[6];
    const float* sw    = (const float*)d_in[7];
    const int*   cutp  = (const int*)d_in[8];

    float* outp = (float*)d_out;            // [4096, 256]
    float* lnp  = outp + NN * HF;           // [4096, 4096]

    kP2<<<dim3(2, 64), 256>>>(nodes, pp, sw);
    kSZ<<<64, 256>>>(ssv, stv);
    kM<<<dim3(32, 32), 256>>>(deg, bond, cutp);
    kA4<<<dim3(4, 32, 4), 128>>>(lnp);
    kC<<<1024, 256>>>(outp);
}

// round 8
// speedup vs baseline: 2.2891x; 2.2891x over previous
#include <cuda_runtime.h>
#include <math.h>
#include <stdint.h>

#define NN 4096
#define FIN 128
#define FOUT 64
#define NHEADS 4
#define HF 256
#define NEG_INF_F (-1e9f)

// ---------------- device scratch ----------------
__device__ float g_mask[NN * NN];                  // 64MB raw mask
__device__ float g_proj[NHEADS * NN * FOUT];       // [h][n][o]
__device__ float g_skip[NN * HF];                  // [n][h*64+o]
__device__ float g_ssrc[NHEADS * NN];
__device__ float g_stgt[NHEADS * NN];
__device__ float g_rowsum[NN];
__device__ float g_rowsq[NN];
__device__ float g_colsum[NHEADS * NN];
__device__ float g_part[4 * NHEADS * NN * FOUT];   // partials (4 j-splits)

// ---------------- helpers ----------------
__device__ __forceinline__ unsigned long long ffma2(unsigned long long a,
                                                    unsigned long long b,
                                                    unsigned long long c) {
    unsigned long long d;
    asm("fma.rn.f32x2 %0, %1, %2, %3;" : "=l"(d) : "l"(a), "l"(b), "l"(c));
    return d;
}
__device__ __forceinline__ unsigned long long dup2(float a) {
    unsigned long long d;
    unsigned int u = __float_as_uint(a);
    asm("mov.b64 %0, {%1, %1};" : "=l"(d) : "r"(u));
    return d;
}
__device__ __forceinline__ float2 unpk(unsigned long long v) {
    unsigned int lo, hi;
    asm("mov.b64 {%0, %1}, %2;" : "=r"(lo), "=r"(hi) : "l"(v));
    return make_float2(__uint_as_float(lo), __uint_as_float(hi));
}
__device__ __forceinline__ uint32_t smem_u32(const void* p) {
    uint32_t a;
    asm("{ .reg .u64 t; cvta.to.shared.u64 t, %1; cvt.u32.u64 %0, t; }"
        : "=r"(a) : "l"(p));
    return a;
}
__device__ __forceinline__ void cp128(uint32_t dst, const void* src) {
    asm volatile("cp.async.cg.shared.global [%0], [%1], 16;"
                 :: "r"(dst), "l"(src) : "memory");
}
#define CP_COMMIT() asm volatile("cp.async.commit_group;" ::: "memory")
#define CP_WAIT(N)  asm volatile("cp.async.wait_group %0;" :: "n"(N) : "memory")

// ---- launch 0: kP2 — nodes @ [proj|skip] -> g_proj, g_skip ----
__global__ __launch_bounds__(256) void kP2(const float* __restrict__ nodes,
                                           const float* __restrict__ pp,
                                           const float* __restrict__ sw) {
    __shared__ float a_s[64 * FIN];   // 32KB
    int t = threadIdx.x;
    int n0 = blockIdx.y * 64;
    int isw = blockIdx.x;
#pragma unroll
    for (int r = 0; r < 32; r++)
        a_s[r * 256 + t] = nodes[n0 * FIN + r * 256 + t];
    __syncthreads();

    float acc[64];
#pragma unroll
    for (int n = 0; n < 64; n++) acc[n] = 0.f;

    if (isw == 0) {
        int h = t >> 6, o = t & 63;
        const float* wcol = pp + h * (FIN * FOUT) + o;
        for (int k4 = 0; k4 < 32; k4++) {
            float w0 = __ldg(&wcol[(4 * k4 + 0) * FOUT]);
            float w1 = __ldg(&wcol[(4 * k4 + 1) * FOUT]);
            float w2 = __ldg(&wcol[(4 * k4 + 2) * FOUT]);
            float w3 = __ldg(&wcol[(4 * k4 + 3) * FOUT]);
#pragma unroll
            for (int n = 0; n < 64; n++) {
                float4 a = *(const float4*)&a_s[n * FIN + 4 * k4];
                acc[n] = fmaf(a.x, w0, acc[n]);
                acc[n] = fmaf(a.y, w1, acc[n]);
                acc[n] = fmaf(a.z, w2, acc[n]);
                acc[n] = fmaf(a.w, w3, acc[n]);
            }
        }
        for (int n = 0; n < 64; n++)
            g_proj[(h * NN + n0 + n) * FOUT + o] = acc[n];
    } else {
        const float* wcol = sw + t * FIN;
        for (int k4 = 0; k4 < 32; k4++) {
            float4 w = __ldg((const float4*)&wcol[4 * k4]);
#pragma unroll
            for (int n = 0; n < 64; n++) {
                float4 a = *(const float4*)&a_s[n * FIN + 4 * k4];
                acc[n] = fmaf(a.x, w.x, acc[n]);
                acc[n] = fmaf(a.y, w.y, acc[n]);
                acc[n] = fmaf(a.z, w.z, acc[n]);
                acc[n] = fmaf(a.w, w.w, acc[n]);
            }
        }
        for (int n = 0; n < 64; n++)
            g_skip[(n0 + n) * HF + t] = acc[n];
    }
}

// ---- launch 1: kSZ — scalar scores + zero accumulators ----
__global__ void kSZ(const float* __restrict__ ssv, const float* __restrict__ stv) {
    int id = blockIdx.x * 256 + threadIdx.x;   // 16384
    g_colsum[id] = 0.f;
    if (id < NN) { g_rowsum[id] = 0.f; g_rowsq[id] = 0.f; }
    int h = id >> 12, n = id & 4095;
    const float4* pr = (const float4*)&g_proj[(h * NN + n) * FOUT];
    const float4* a = (const float4*)(ssv + h * FOUT);
    const float4* b = (const float4*)(stv + h * FOUT);
    float s1 = 0.f, s2 = 0.f;
#pragma unroll
    for (int q = 0; q < 16; q++) {
        float4 p = pr[q];
        float4 av = __ldg(&a[q]);
        float4 bv = __ldg(&b[q]);
        s1 += p.x * av.x + p.y * av.y + p.z * av.z + p.w * av.w;
        s2 += p.x * bv.x + p.y * bv.y + p.z * bv.z + p.w * bv.w;
    }
    g_ssrc[id] = s1;
    g_stgt[id] = s2;
}

// ---- launch 2: kM — mask + row stats + column exp-sums ----
__global__ __launch_bounds__(256) void kM(const float* __restrict__ deg,
                                          const float* __restrict__ bond,
                                          const int* __restrict__ cutp) {
    __shared__ float cs[NHEADS][128];
    int t = threadIdx.x;
    int col = t & 127, half = t >> 7;
    int j0 = blockIdx.x * 128, i0 = blockIdx.y * 128;
    float cut = (float)__ldg(cutp);
    float st[NHEADS], acc[NHEADS];
#pragma unroll
    for (int h = 0; h < NHEADS; h++) {
        st[h] = __ldg(&g_stgt[h * NN + j0 + col]);
        acc[h] = 0.f;
    }
    for (int s = 0; s < 64; s++) {
        int gi = i0 + 2 * s + half;
        int g = gi * NN + j0 + col;
        float d = deg[g], b = bond[g];
        float wdm = d + b;
        float m = (wdm > 0.f) ? wdm : ((b > cut) ? (b + wdm) : NEG_INF_F);
        g_mask[g] = m;
        float s1 = m, s2 = m * m;
#pragma unroll
        for (int off = 16; off; off >>= 1) {
            s1 += __shfl_down_sync(0xffffffffu, s1, off);
            s2 += __shfl_down_sync(0xffffffffu, s2, off);
        }
        if ((t & 31) == 0) {
            atomicAdd(&g_rowsum[gi], s1);
            atomicAdd(&g_rowsq[gi], s2);
        }
#pragma unroll
        for (int h = 0; h < NHEADS; h++) {
            float x = __ldg(&g_ssrc[h * NN + gi]) + st[h];
            float lr = fmaxf(x, 0.2f * x);
            acc[h] += __expf(lr + m);
        }
    }
    if (half == 1) {
#pragma unroll
        for (int h = 0; h < NHEADS; h++) cs[h][col] = acc[h];
    }
    __syncthreads();
    if (half == 0) {
#pragma unroll
        for (int h = 0; h < NHEADS; h++)
            atomicAdd(&g_colsum[h * NN + j0 + col], acc[h] + cs[h][col]);
    }
}

// ---- launch 3: kA6 — cp.async-staged fused attn-gen + GEMM + mask_ln ----
// grid (4h, 16it, 4js) = 256 CTAs, 256 thr, 2 CTAs/SM.
// Tile 256i x 64f, K-span 1024j in 32 chunks of 32j.
// Dynamic smem: at[256*33] | mstage[2][256*32] | pstage[32*64] | sss|smu|sis
#define ATP 33
#define AT_OFF   0
#define MST_OFF  33792
#define PST_OFF  (33792 + 65536)
#define SSS_OFF  (PST_OFF + 8192)
#define SMU_OFF  (SSS_OFF + 1024)
#define SIS_OFF  (SMU_OFF + 1024)
#define SMEM_TOT (SIS_OFF + 1024)
__global__ __launch_bounds__(256, 2) void kA6(float* __restrict__ lnp) {
    extern __shared__ char dsm[];
    float* at  = (float*)(dsm + AT_OFF);
    float* mst = (float*)(dsm + MST_OFF);
    float* pst = (float*)(dsm + PST_OFF);
    float* sss = (float*)(dsm + SSS_OFF);
    float* smu = (float*)(dsm + SMU_OFF);
    float* sis = (float*)(dsm + SIS_OFF);
    uint32_t mst_u = smem_u32(mst);
    uint32_t pst_u = smem_u32(pst);

    int t = threadIdx.x;
    int h = blockIdx.x;
    int i0 = blockIdx.y * 256;
    int jbase = blockIdx.z * 1024;
    bool do_ln = (h == 0);

    // per-CTA init
    sss[t] = __ldg(&g_ssrc[h * NN + i0 + t]);
    if (do_ln) {
        float mu = g_rowsum[i0 + t] * (1.0f / NN);
        float var = fmaxf(g_rowsq[i0 + t] * (1.0f / NN) - mu * mu, 0.f);
        smu[t] = mu;
        sis[t] = rsqrtf(var + 1e-5f);
    }

    // prologue: stage mask chunk 0 (row t of 256, 32 floats = 8 x 16B)
    {
        const float* src = g_mask + (size_t)(i0 + t) * NN + jbase;
        uint32_t dst = mst_u + t * 128;
#pragma unroll
        for (int q = 0; q < 8; q++) cp128(dst + q * 16, src + q * 4);
        CP_COMMIT();
    }

    // fill indices
    int jf = t & 31, ig = t >> 5;
    // proj-copy indices
    int prow = t >> 3, pseg = t & 7;
    // gemm indices
    int tx = t & 7, ty = t >> 3;
    int f0 = 4 * tx, iA = 4 * ty;

    unsigned long long acc[8][4];
#pragma unroll
    for (int r = 0; r < 8; r++)
#pragma unroll
        for (int c = 0; c < 4; c++) acc[r][c] = 0ull;

    const float* stb = g_stgt + h * NN;
    const float* csb = g_colsum + h * NN;

    for (int c = 0; c < 32; c++) {
        int buf = c & 1;
        int j0 = jbase + c * 32;
        CP_WAIT(0);          // own M(c) copies complete (c=0) / M(c) (steady)
        __syncthreads();     // all M(c) visible; GEMM(c-1) finished
        // issue P(c): proj tile 32j x 64f (thread: row prow, 32B seg pseg)
        {
            const float* src =
                g_proj + (size_t)(h * NN + j0 + prow) * FOUT + pseg * 8;
            uint32_t dst = pst_u + (prow * FOUT + pseg * 8) * 4;
            cp128(dst, src);
            cp128(dst + 16, src + 4);
            CP_COMMIT();
        }
        // issue M(c+1) (wrap for c=31; data unused)
        {
            int j0n = jbase + ((c + 1) & 31) * 32;
            const float* src = g_mask + (size_t)(i0 + t) * NN + j0n;
            uint32_t dst = mst_u + (buf ^ 1) * 32768 + t * 128;
#pragma unroll
            for (int q = 0; q < 8; q++) cp128(dst + q * 16, src + q * 4);
            CP_COMMIT();
        }
        // fill at from staged mask: at[i][jf] = exp(leaky+mask) / colsum[j]
        {
            float stv = __ldg(&stb[j0 + jf]);
            float cvv = __fdividef(1.0f, __ldg(&csb[j0 + jf]));
            const float* ms = mst + buf * 8192;
#pragma unroll 4
            for (int r = 0; r < 32; r++) {
                int i = ig * 32 + r;
                float m = ms[i * 32 + jf];
                float x = sss[i] + stv;
                float lr = fmaxf(x, 0.2f * x);
                at[i * ATP + jf] = __expf(lr + m) * cvv;
                if (do_ln)
                    lnp[(size_t)(i0 + i) * NN + j0 + jf] = (m - smu[i]) * sis[i];
            }
        }
        CP_WAIT(1);          // P(c) done (older than M(c+1)); M(c+1) in flight
        __syncthreads();     // at + pstage visible to all
        // GEMM: 8i x 8f per thread over 32 kk
#pragma unroll 4
        for (int kk = 0; kk < 32; kk++) {
            const float* ab = at + kk;
            ulonglong2 bL = *(const ulonglong2*)&pst[kk * FOUT + f0];
            ulonglong2 bH = *(const ulonglong2*)&pst[kk * FOUT + f0 + 32];
            unsigned long long d;
            float a0 = ab[(iA + 0) * ATP];
            float a1 = ab[(iA + 1) * ATP];
            float a2 = ab[(iA + 2) * ATP];
            float a3 = ab[(iA + 3) * ATP];
            float a4 = ab[(iA + 128) * ATP];
            float a5 = ab[(iA + 129) * ATP];
            float a6 = ab[(iA + 130) * ATP];
            float a7 = ab[(iA + 131) * ATP];
            d = dup2(a0);
            acc[0][0] = ffma2(d, bL.x, acc[0][0]); acc[0][1] = ffma2(d, bL.y, acc[0][1]);
            acc[0][2] = ffma2(d, bH.x, acc[0][2]); acc[0][3] = ffma2(d, bH.y, acc[0][3]);
            d = dup2(a1);
            acc[1][0] = ffma2(d, bL.x, acc[1][0]); acc[1][1] = ffma2(d, bL.y, acc[1][1]);
            acc[1][2] = ffma2(d, bH.x, acc[1][2]); acc[1][3] = ffma2(d, bH.y, acc[1][3]);
            d = dup2(a2);
            acc[2][0] = ffma2(d, bL.x, acc[2][0]); acc[2][1] = ffma2(d, bL.y, acc[2][1]);
            acc[2][2] = ffma2(d, bH.x, acc[2][2]); acc[2][3] = ffma2(d, bH.y, acc[2][3]);
            d = dup2(a3);
            acc[3][0] = ffma2(d, bL.x, acc[3][0]); acc[3][1] = ffma2(d, bL.y, acc[3][1]);
            acc[3][2] = ffma2(d, bH.x, acc[3][2]); acc[3][3] = ffma2(d, bH.y, acc[3][3]);
            d = dup2(a4);
            acc[4][0] = ffma2(d, bL.x, acc[4][0]); acc[4][1] = ffma2(d, bL.y, acc[4][1]);
            acc[4][2] = ffma2(d, bH.x, acc[4][2]); acc[4][3] = ffma2(d, bH.y, acc[4][3]);
            d = dup2(a5);
            acc[5][0] = ffma2(d, bL.x, acc[5][0]); acc[5][1] = ffma2(d, bL.y, acc[5][1]);
            acc[5][2] = ffma2(d, bH.x, acc[5][2]); acc[5][3] = ffma2(d, bH.y, acc[5][3]);
            d = dup2(a6);
            acc[6][0] = ffma2(d, bL.x, acc[6][0]); acc[6][1] = ffma2(d, bL.y, acc[6][1]);
            acc[6][2] = ffma2(d, bH.x, acc[6][2]); acc[6][3] = ffma2(d, bH.y, acc[6][3]);
            d = dup2(a7);
            acc[7][0] = ffma2(d, bL.x, acc[7][0]); acc[7][1] = ffma2(d, bL.y, acc[7][1]);
            acc[7][2] = ffma2(d, bH.x, acc[7][2]); acc[7][3] = ffma2(d, bH.y, acc[7][3]);
        }
    }
    // store partials: rows iA+0..3 and iA+128..131
    float* pbase = g_part + ((size_t)(blockIdx.z * NHEADS + h)) * (NN * FOUT);
#pragma unroll
    for (int r = 0; r < 8; r++) {
        int gi = i0 + iA + (r < 4 ? r : 124 + r);
        float2 lo0 = unpk(acc[r][0]);
        float2 hi0 = unpk(acc[r][1]);
        float2 lo1 = unpk(acc[r][2]);
        float2 hi1 = unpk(acc[r][3]);
        *(float4*)&pbase[gi * FOUT + f0] = make_float4(lo0.x, lo0.y, hi0.x, hi0.y);
        *(float4*)&pbase[gi * FOUT + f0 + 32] = make_float4(lo1.x, lo1.y, hi1.x, hi1.y);
    }
}

// ---- launch 4: kC — combine 4 partials + skip + ELU ----
__global__ void kC(float* __restrict__ outp) {
    int id = blockIdx.x * 256 + threadIdx.x;   // 0 .. 262143
    int nf = id * 4;
    int n = nf >> 8;
    int c = nf & 255;
    int h = c >> 6, f = c & 63;
    size_t base = ((size_t)h * NN + n) * FOUT + f;
    const size_t stride = (size_t)NHEADS * NN * FOUT;
    float4 p0 = *(const float4*)&g_part[base];
    float4 p1 = *(const float4*)&g_part[base + stride];
    float4 p2 = *(const float4*)&g_part[base + 2 * stride];
    float4 p3 = *(const float4*)&g_part[base + 3 * stride];
    float4 sk = *(const float4*)&g_skip[n * HF + c];
    float v0 = (p0.x + p1.x) + (p2.x + p3.x) + sk.x;
    float v1 = (p0.y + p1.y) + (p2.y + p3.y) + sk.y;
    float v2 = (p0.z + p1.z) + (p2.z + p3.z) + sk.z;
    float v3 = (p0.w + p1.w) + (p2.w + p3.w) + sk.w;
    v0 = v0 > 0.f ? v0 : expm1f(v0);
    v1 = v1 > 0.f ? v1 : expm1f(v1);
    v2 = v2 > 0.f ? v2 : expm1f(v2);
    v3 = v3 > 0.f ? v3 : expm1f(v3);
    *(float4*)&outp[nf] = make_float4(v0, v1, v2, v3);
}

// ---------------- host launch ----------------
extern "C" void kernel_launch(void* const* d_in, const int* in_sizes, int n_in,
                              void* d_out, int out_size) {
    const float* nodes = (const float*)d_in[0];
    const float* deg   = (const float*)d_in[1];
    const float* bond  = (const float*)d_in[3];
    const float* pp    = (const float*)d_in[4];
    const float* ssv   = (const float*)d_in[5];
    const float* stv   = (const float*)d_in[6];
    const float* sw    = (const float*)d_in[7];
    const int*   cutp  = (const int*)d_in[8];

    float* outp = (float*)d_out;            // [4096, 256]
    float* lnp  = outp + NN * HF;           // [4096, 4096]

    cudaFuncSetAttribute(kA6, cudaFuncAttributeMaxDynamicSharedMemorySize,
                         SMEM_TOT);

    kP2<<<dim3(2, 64), 256>>>(nodes, pp, sw);
    kSZ<<<64, 256>>>(ssv, stv);
    kM<<<dim3(32, 32), 256>>>(deg, bond, cutp);
    kA6<<<dim3(4, 16, 4), 256, SMEM_TOT>>>(lnp);
    kC<<<1024, 256>>>(outp);
}

// round 10
// speedup vs baseline: 2.4495x; 1.0701x over previous
#include <cuda_runtime.h>
#include <cuda_bf16.h>
#include <math.h>
#include <stdint.h>

#define NN 4096
#define FIN 128
#define FOUT 64
#define NHEADS 4
#define HF 256
#define NEG_INF_F (-1e9f)

// ---------------- device scratch ----------------
__device__ float g_mask[NN * NN];                  // 64MB raw mask
__device__ float g_proj[NHEADS * NN * FOUT];       // [h][n][o]
__device__ float g_skip[NN * HF];                  // [n][h*64+o]
__device__ float g_ssrc[NHEADS * NN];
__device__ float g_stgt[NHEADS * NN];
__device__ float g_rowsum[NN];
__device__ float g_rowsq[NN];
__device__ float g_colsum[NHEADS * NN];
__device__ float g_part[4 * NHEADS * NN * FOUT];   // partials (4 j-splits)

// ---------------- helpers ----------------
__device__ __forceinline__ uint32_t smem_u32(const void* p) {
    uint32_t a;
    asm("{ .reg .u64 t; cvta.to.shared.u64 t, %1; cvt.u32.u64 %0, t; }"
        : "=r"(a) : "l"(p));
    return a;
}
__device__ __forceinline__ void cp128(uint32_t dst, const void* src) {
    asm volatile("cp.async.cg.shared.global [%0], [%1], 16;"
                 :: "r"(dst), "l"(src) : "memory");
}
#define CP_COMMIT() asm volatile("cp.async.commit_group;" ::: "memory")
#define CP_WAIT(N)  asm volatile("cp.async.wait_group %0;" :: "n"(N) : "memory")

#define LDSM4(R, addr) \
    asm volatile("ldmatrix.sync.aligned.m8n8.x4.shared.b16 {%0,%1,%2,%3}, [%4];" \
                 : "=r"((R)[0]), "=r"((R)[1]), "=r"((R)[2]), "=r"((R)[3]) \
                 : "r"(addr))
#define LDSM4T(R, addr) \
    asm volatile("ldmatrix.sync.aligned.m8n8.x4.trans.shared.b16 {%0,%1,%2,%3}, [%4];" \
                 : "=r"((R)[0]), "=r"((R)[1]), "=r"((R)[2]), "=r"((R)[3]) \
                 : "r"(addr))
#define MMA16816(C, A, b0, b1) \
    asm volatile("mma.sync.aligned.m16n8k16.row.col.f32.bf16.bf16.f32 " \
                 "{%0,%1,%2,%3}, {%4,%5,%6,%7}, {%8,%9}, {%0,%1,%2,%3};" \
                 : "+f"((C)[0]), "+f"((C)[1]), "+f"((C)[2]), "+f"((C)[3]) \
                 : "r"((A)[0]), "r"((A)[1]), "r"((A)[2]), "r"((A)[3]), \
                   "r"(b0), "r"(b1))

// ---- launch 0: kP2 — nodes @ [proj|skip] -> g_proj, g_skip ----
__global__ __launch_bounds__(256) void kP2(const float* __restrict__ nodes,
                                           const float* __restrict__ pp,
                                           const float* __restrict__ sw) {
    __shared__ float a_s[64 * FIN];
    int t = threadIdx.x;
    int n0 = blockIdx.y * 64;
    int isw = blockIdx.x;
#pragma unroll
    for (int r = 0; r < 32; r++)
        a_s[r * 256 + t] = nodes[n0 * FIN + r * 256 + t];
    __syncthreads();

    float acc[64];
#pragma unroll
    for (int n = 0; n < 64; n++) acc[n] = 0.f;

    if (isw == 0) {
        int h = t >> 6, o = t & 63;
        const float* wcol = pp + h * (FIN * FOUT) + o;
        for (int k4 = 0; k4 < 32; k4++) {
            float w0 = __ldg(&wcol[(4 * k4 + 0) * FOUT]);
            float w1 = __ldg(&wcol[(4 * k4 + 1) * FOUT]);
            float w2 = __ldg(&wcol[(4 * k4 + 2) * FOUT]);
            float w3 = __ldg(&wcol[(4 * k4 + 3) * FOUT]);
#pragma unroll
            for (int n = 0; n < 64; n++) {
                float4 a = *(const float4*)&a_s[n * FIN + 4 * k4];
                acc[n] = fmaf(a.x, w0, acc[n]);
                acc[n] = fmaf(a.y, w1, acc[n]);
                acc[n] = fmaf(a.z, w2, acc[n]);
                acc[n] = fmaf(a.w, w3, acc[n]);
            }
        }
        for (int n = 0; n < 64; n++)
            g_proj[(h * NN + n0 + n) * FOUT + o] = acc[n];
    } else {
        const float* wcol = sw + t * FIN;
        for (int k4 = 0; k4 < 32; k4++) {
            float4 w = __ldg((const float4*)&wcol[4 * k4]);
#pragma unroll
            for (int n = 0; n < 64; n++) {
                float4 a = *(const float4*)&a_s[n * FIN + 4 * k4];
                acc[n] = fmaf(a.x, w.x, acc[n]);
                acc[n] = fmaf(a.y, w.y, acc[n]);
                acc[n] = fmaf(a.z, w.z, acc[n]);
                acc[n] = fmaf(a.w, w.w, acc[n]);
            }
        }
        for (int n = 0; n < 64; n++)
            g_skip[(n0 + n) * HF + t] = acc[n];
    }
}

// ---- launch 1: kSZ — scalar scores + zero accumulators ----
__global__ void kSZ(const float* __restrict__ ssv, const float* __restrict__ stv) {
    int id = blockIdx.x * 256 + threadIdx.x;
    g_colsum[id] = 0.f;
    if (id < NN) { g_rowsum[id] = 0.f; g_rowsq[id] = 0.f; }
    int h = id >> 12, n = id & 4095;
    const float4* pr = (const float4*)&g_proj[(h * NN + n) * FOUT];
    const float4* a = (const float4*)(ssv + h * FOUT);
    const float4* b = (const float4*)(stv + h * FOUT);
    float s1 = 0.f, s2 = 0.f;
#pragma unroll
    for (int q = 0; q < 16; q++) {
        float4 p = pr[q];
        float4 av = __ldg(&a[q]);
        float4 bv = __ldg(&b[q]);
        s1 += p.x * av.x + p.y * av.y + p.z * av.z + p.w * av.w;
        s2 += p.x * bv.x + p.y * bv.y + p.z * bv.z + p.w * bv.w;
    }
    g_ssrc[id] = s1;
    g_stgt[id] = s2;
}

// ---- launch 2: kM — mask + row stats + column exp-sums ----
__global__ __launch_bounds__(256) void kM(const float* __restrict__ deg,
                                          const float* __restrict__ bond,
                                          const int* __restrict__ cutp) {
    __shared__ float cs[NHEADS][128];
    int t = threadIdx.x;
    int col = t & 127, half = t >> 7;
    int j0 = blockIdx.x * 128, i0 = blockIdx.y * 128;
    float cut = (float)__ldg(cutp);
    float st[NHEADS], acc[NHEADS];
#pragma unroll
    for (int h = 0; h < NHEADS; h++) {
        st[h] = __ldg(&g_stgt[h * NN + j0 + col]);
        acc[h] = 0.f;
    }
    for (int s = 0; s < 64; s++) {
        int gi = i0 + 2 * s + half;
        int g = gi * NN + j0 + col;
        float d = deg[g], b = bond[g];
        float wdm = d + b;
        float m = (wdm > 0.f) ? wdm : ((b > cut) ? (b + wdm) : NEG_INF_F);
        g_mask[g] = m;
        float s1 = m, s2 = m * m;
#pragma unroll
        for (int off = 16; off; off >>= 1) {
            s1 += __shfl_down_sync(0xffffffffu, s1, off);
            s2 += __shfl_down_sync(0xffffffffu, s2, off);
        }
        if ((t & 31) == 0) {
            atomicAdd(&g_rowsum[gi], s1);
            atomicAdd(&g_rowsq[gi], s2);
        }
#pragma unroll
        for (int h = 0; h < NHEADS; h++) {
            float x = __ldg(&g_ssrc[h * NN + gi]) + st[h];
            float lr = fmaxf(x, 0.2f * x);
            acc[h] += __expf(lr + m);
        }
    }
    if (half == 1) {
#pragma unroll
        for (int h = 0; h < NHEADS; h++) cs[h][col] = acc[h];
    }
    __syncthreads();
    if (half == 0) {
#pragma unroll
        for (int h = 0; h < NHEADS; h++)
            atomicAdd(&g_colsum[h * NN + j0 + col], acc[h] + cs[h][col]);
    }
}

// ---- launch 3: kA7 — cp.async staging + bf16 mma.sync GEMM + mask_ln ----
// grid (4h, 16it, 4js) = 256 CTAs, 256 thr. Tile 256i x 64f, K 1024j, 32-chunks.
// smem: mst fp32 x2 | pstg fp32 x2 | at bf16 (pitch 80B) | bst bf16 (pitch 144B)
#define MST_OFF  0
#define PST_OFF  65536
#define AT_OFF   81920
#define BST_OFF  102400
#define SSS_OFF  107008
#define SMU_OFF  108032
#define SIS_OFF  109056
#define SMEM_TOT 110080
__global__ __launch_bounds__(256, 2) void kA7(float* __restrict__ lnp) {
    extern __shared__ char dsm[];
    float* sss = (float*)(dsm + SSS_OFF);
    float* smu = (float*)(dsm + SMU_OFF);
    float* sis = (float*)(dsm + SIS_OFF);
    uint32_t mst_u = smem_u32(dsm + MST_OFF);
    uint32_t pst_u = smem_u32(dsm + PST_OFF);
    uint32_t at_u  = smem_u32(dsm + AT_OFF);
    uint32_t bst_u = smem_u32(dsm + BST_OFF);

    int t = threadIdx.x;
    int h = blockIdx.x;
    int i0 = blockIdx.y * 256;
    int jbase = blockIdx.z * 1024;
    bool do_ln = (h == 0);

    sss[t] = __ldg(&g_ssrc[h * NN + i0 + t]);
    if (do_ln) {
        float mu = g_rowsum[i0 + t] * (1.0f / NN);
        float var = fmaxf(g_rowsq[i0 + t] * (1.0f / NN) - mu * mu, 0.f);
        smu[t] = mu;
        sis[t] = rsqrtf(var + 1e-5f);
    }

    int pk = t >> 3, pseg = t & 7;         // proj stage: row pk, 32B seg pseg
    // prologue: stage M(0) + P(0)
    {
        const float* msrc = g_mask + (size_t)(i0 + t) * NN + jbase;
        uint32_t mdst = mst_u + t * 128;
#pragma unroll
        for (int q = 0; q < 8; q++) cp128(mdst + q * 16, msrc + q * 4);
        const float* psrc = g_proj + (size_t)(h * NN + jbase + pk) * FOUT + pseg * 8;
        uint32_t pdst = pst_u + pk * 256 + pseg * 32;
        cp128(pdst, psrc);
        cp128(pdst + 16, psrc + 4);
        CP_COMMIT();
    }

    int jp = t & 15, ir = t >> 4;          // fill: 16 j-pairs x 16 i-groups
    int w = t >> 5, l = t & 31;            // gemm warp/lane

    float acc0[8][4], acc1[8][4];
#pragma unroll
    for (int n = 0; n < 8; n++)
#pragma unroll
        for (int q = 0; q < 4; q++) { acc0[n][q] = 0.f; acc1[n][q] = 0.f; }

    const float* stb = g_stgt + h * NN;
    const float* csb = g_colsum + h * NN;

    uint32_t a_base = at_u + (w * 32 + (l & 15)) * 80 + (l >> 4) * 16;
    uint32_t b_base = bst_u + (l & 15) * 144 + (l >> 4) * 16;

    for (int c = 0; c < 32; c++) {
        int buf = c & 1;
        int j0 = jbase + c * 32;
        CP_WAIT(0);
        __syncthreads();
        // stage next chunk into buf^1 (overlaps fill + GEMM)
        {
            int j0n = jbase + ((c + 1) & 31) * 32;
            const float* msrc = g_mask + (size_t)(i0 + t) * NN + j0n;
            uint32_t mdst = mst_u + (buf ^ 1) * 32768 + t * 128;
#pragma unroll
            for (int q = 0; q < 8; q++) cp128(mdst + q * 16, msrc + q * 4);
            const float* psrc = g_proj + (size_t)(h * NN + j0n + pk) * FOUT + pseg * 8;
            uint32_t pdst = pst_u + (buf ^ 1) * 8192 + pk * 256 + pseg * 32;
            cp128(pdst, psrc);
            cp128(pdst + 16, psrc + 4);
            CP_COMMIT();
        }
        // fill at (bf16): at[i][j] = exp(leaky(ssrc+stgt)+mask)
        {
            float st0 = __ldg(&stb[j0 + 2 * jp]);
            float st1 = __ldg(&stb[j0 + 2 * jp + 1]);
            const float* ms = (const float*)(dsm + MST_OFF + buf * 32768);
#pragma unroll 4
            for (int r = 0; r < 16; r++) {
                int i = ir * 16 + r;
                float2 mm = *(const float2*)(ms + i * 32 + 2 * jp);
                float s = sss[i];
                float x0 = s + st0, x1 = s + st1;
                float a0 = __expf(fmaxf(x0, 0.2f * x0) + mm.x);
                float a1 = __expf(fmaxf(x1, 0.2f * x1) + mm.y);
                *(__nv_bfloat162*)(dsm + AT_OFF + i * 80 + jp * 4) =
                    __floats2bfloat162_rn(a0, a1);
                if (do_ln)
                    *(float2*)&lnp[(size_t)(i0 + i) * NN + j0 + 2 * jp] =
                        make_float2((mm.x - smu[i]) * sis[i],
                                    (mm.y - smu[i]) * sis[i]);
            }
        }
        // convert b (bf16): bst[k][n] = proj[k][n] / colsum[k]
        {
            float cvv = __fdividef(1.0f, __ldg(&csb[j0 + pk]));
            const float* ps =
                (const float*)(dsm + PST_OFF + buf * 8192) + pk * 64 + pseg * 8;
            float4 p0 = *(const float4*)ps;
            float4 p1 = *(const float4*)(ps + 4);
            __nv_bfloat162 b0 = __floats2bfloat162_rn(p0.x * cvv, p0.y * cvv);
            __nv_bfloat162 b1 = __floats2bfloat162_rn(p0.z * cvv, p0.w * cvv);
            __nv_bfloat162 b2 = __floats2bfloat162_rn(p1.x * cvv, p1.y * cvv);
            __nv_bfloat162 b3 = __floats2bfloat162_rn(p1.z * cvv, p1.w * cvv);
            uint4 pk4;
            pk4.x = *(uint32_t*)&b0; pk4.y = *(uint32_t*)&b1;
            pk4.z = *(uint32_t*)&b2; pk4.w = *(uint32_t*)&b3;
            *(uint4*)(dsm + BST_OFF + pk * 144 + pseg * 16) = pk4;
        }
        __syncthreads();
        // GEMM: warp tile 32i x 64f, two k-steps of 16
#pragma unroll
        for (int ks = 0; ks < 2; ks++) {
            uint32_t A0[4], A1[4];
            LDSM4(A0, a_base + ks * 32);
            LDSM4(A1, a_base + ks * 32 + 16 * 80);
#pragma unroll
            for (int nb = 0; nb < 4; nb++) {
                uint32_t B[4];
                LDSM4T(B, b_base + ks * 2304 + nb * 32);
                MMA16816(acc0[2 * nb],     A0, B[0], B[1]);
                MMA16816(acc0[2 * nb + 1], A0, B[2], B[3]);
                MMA16816(acc1[2 * nb],     A1, B[0], B[1]);
                MMA16816(acc1[2 * nb + 1], A1, B[2], B[3]);
            }
        }
    }
    // epilogue: write partials
    float* pbase = g_part + ((size_t)(blockIdx.z * NHEADS + h)) * (NN * FOUT);
    int g = l >> 2, tg = l & 3;
#pragma unroll
    for (int mi = 0; mi < 2; mi++) {
        float(*am)[4] = mi ? acc1 : acc0;
        int row0 = i0 + w * 32 + mi * 16 + g;
#pragma unroll
        for (int nf = 0; nf < 8; nf++) {
            int f = nf * 8 + tg * 2;
            *(float2*)&pbase[(size_t)row0 * FOUT + f] =
                make_float2(am[nf][0], am[nf][1]);
            *(float2*)&pbase[(size_t)(row0 + 8) * FOUT + f] =
                make_float2(am[nf][2], am[nf][3]);
        }
    }
}

// ---- launch 4: kC — combine 4 partials + skip + ELU ----
__global__ void kC(float* __restrict__ outp) {
    int id = blockIdx.x * 256 + threadIdx.x;
    int nf = id * 4;
    int n = nf >> 8;
    int c = nf & 255;
    int h = c >> 6, f = c & 63;
    size_t base = ((size_t)h * NN + n) * FOUT + f;
    const size_t stride = (size_t)NHEADS * NN * FOUT;
    float4 p0 = *(const float4*)&g_part[base];
    float4 p1 = *(const float4*)&g_part[base + stride];
    float4 p2 = *(const float4*)&g_part[base + 2 * stride];
    float4 p3 = *(const float4*)&g_part[base + 3 * stride];
    float4 sk = *(const float4*)&g_skip[n * HF + c];
    float v0 = (p0.x + p1.x) + (p2.x + p3.x) + sk.x;
    float v1 = (p0.y + p1.y) + (p2.y + p3.y) + sk.y;
    float v2 = (p0.z + p1.z) + (p2.z + p3.z) + sk.z;
    float v3 = (p0.w + p1.w) + (p2.w + p3.w) + sk.w;
    v0 = v0 > 0.f ? v0 : expm1f(v0);
    v1 = v1 > 0.f ? v1 : expm1f(v1);
    v2 = v2 > 0.f ? v2 : expm1f(v2);
    v3 = v3 > 0.f ? v3 : expm1f(v3);
    *(float4*)&outp[nf] = make_float4(v0, v1, v2, v3);
}

// ---------------- host launch ----------------
extern "C" void kernel_launch(void* const* d_in, const int* in_sizes, int n_in,
                              void* d_out, int out_size) {
    const float* nodes = (const float*)d_in[0];
    const float* deg   = (const float*)d_in[1];
    const float* bond  = (const float*)d_in[3];
    const float* pp    = (const float*)d_in[4];
    const float* ssv   = (const float*)d_in[5];
    const float* stv   = (const float*)d_in[6];
    const float* sw    = (const float*)d_in[7];
    const int*   cutp  = (const int*)d_in[8];

    float* outp = (float*)d_out;            // [4096, 256]
    float* lnp  = outp + NN * HF;           // [4096, 4096]

    cudaFuncSetAttribute(kA7, cudaFuncAttributeMaxDynamicSharedMemorySize,
                         SMEM_TOT);

    kP2<<<dim3(2, 64), 256>>>(nodes, pp, sw);
    kSZ<<<64, 256>>>(ssv, stv);
    kM<<<dim3(32, 32), 256>>>(deg, bond, cutp);
    kA7<<<dim3(4, 16, 4), 256, SMEM_TOT>>>(lnp);
    kC<<<1024, 256>>>(outp);
}

// round 12
// speedup vs baseline: 3.9306x; 1.6046x over previous
#include <cuda_runtime.h>
#include <cuda_bf16.h>
#include <math.h>
#include <stdint.h>

#define NN 4096
#define FIN 128
#define FOUT 64
#define NHEADS 4
#define HF 256
#define NEG_INF_F (-1e9f)

// ---------------- device scratch ----------------
__device__ float g_mask[NN * NN];                   // 64MB raw mask
__device__ __nv_bfloat16 g_attn[(size_t)NHEADS * NN * NN];  // 134MB bf16 numerator
__device__ float g_proj[NHEADS * NN * FOUT];        // [h][n][o]
__device__ __nv_bfloat16 g_projB[NHEADS * NN * FOUT];  // bf16 proj/colsum
__device__ float g_skip[NN * HF];                   // [n][h*64+o]
__device__ float g_ssrc[NHEADS * NN];
__device__ float g_stgt[NHEADS * NN];
__device__ float g_rowsum[NN];
__device__ float g_rowsq[NN];
__device__ float g_colsum[NHEADS * NN];
__device__ float g_part[8 * NHEADS * NN * FOUT];    // 33.5MB partials (8 j-splits)

// ---------------- helpers ----------------
__device__ __forceinline__ uint32_t smem_u32(const void* p) {
    uint32_t a;
    asm("{ .reg .u64 t; cvta.to.shared.u64 t, %1; cvt.u32.u64 %0, t; }"
        : "=r"(a) : "l"(p));
    return a;
}
__device__ __forceinline__ void cp128(uint32_t dst, const void* src) {
    asm volatile("cp.async.cg.shared.global [%0], [%1], 16;"
                 :: "r"(dst), "l"(src) : "memory");
}
#define CP_COMMIT() asm volatile("cp.async.commit_group;" ::: "memory")
#define CP_WAIT(N)  asm volatile("cp.async.wait_group %0;" :: "n"(N) : "memory")

#define LDSM4(R, addr) \
    asm volatile("ldmatrix.sync.aligned.m8n8.x4.shared.b16 {%0,%1,%2,%3}, [%4];" \
                 : "=r"((R)[0]), "=r"((R)[1]), "=r"((R)[2]), "=r"((R)[3]) \
                 : "r"(addr))
#define LDSM4T(R, addr) \
    asm volatile("ldmatrix.sync.aligned.m8n8.x4.trans.shared.b16 {%0,%1,%2,%3}, [%4];" \
                 : "=r"((R)[0]), "=r"((R)[1]), "=r"((R)[2]), "=r"((R)[3]) \
                 : "r"(addr))
#define MMA16816(C, A, b0, b1) \
    asm volatile("mma.sync.aligned.m16n8k16.row.col.f32.bf16.bf16.f32 " \
                 "{%0,%1,%2,%3}, {%4,%5,%6,%7}, {%8,%9}, {%0,%1,%2,%3};" \
                 : "+f"((C)[0]), "+f"((C)[1]), "+f"((C)[2]), "+f"((C)[3]) \
                 : "r"((A)[0]), "r"((A)[1]), "r"((A)[2]), "r"((A)[3]), \
                   "r"(b0), "r"(b1))

// ---- launch 0: kP2 — nodes @ [proj|skip] -> g_proj, g_skip ----
__global__ __launch_bounds__(256) void kP2(const float* __restrict__ nodes,
                                           const float* __restrict__ pp,
                                           const float* __restrict__ sw) {
    __shared__ float a_s[64 * FIN];
    int t = threadIdx.x;
    int n0 = blockIdx.y * 64;
    int isw = blockIdx.x;
#pragma unroll
    for (int r = 0; r < 32; r++)
        a_s[r * 256 + t] = nodes[n0 * FIN + r * 256 + t];
    __syncthreads();

    float acc[64];
#pragma unroll
    for (int n = 0; n < 64; n++) acc[n] = 0.f;

    if (isw == 0) {
        int h = t >> 6, o = t & 63;
        const float* wcol = pp + h * (FIN * FOUT) + o;
        for (int k4 = 0; k4 < 32; k4++) {
            float w0 = __ldg(&wcol[(4 * k4 + 0) * FOUT]);
            float w1 = __ldg(&wcol[(4 * k4 + 1) * FOUT]);
            float w2 = __ldg(&wcol[(4 * k4 + 2) * FOUT]);
            float w3 = __ldg(&wcol[(4 * k4 + 3) * FOUT]);
#pragma unroll
            for (int n = 0; n < 64; n++) {
                float4 a = *(const float4*)&a_s[n * FIN + 4 * k4];
                acc[n] = fmaf(a.x, w0, acc[n]);
                acc[n] = fmaf(a.y, w1, acc[n]);
                acc[n] = fmaf(a.z, w2, acc[n]);
                acc[n] = fmaf(a.w, w3, acc[n]);
            }
        }
        for (int n = 0; n < 64; n++)
            g_proj[(h * NN + n0 + n) * FOUT + o] = acc[n];
    } else {
        const float* wcol = sw + t * FIN;
        for (int k4 = 0; k4 < 32; k4++) {
            float4 w = __ldg((const float4*)&wcol[4 * k4]);
#pragma unroll
            for (int n = 0; n < 64; n++) {
                float4 a = *(const float4*)&a_s[n * FIN + 4 * k4];
                acc[n] = fmaf(a.x, w.x, acc[n]);
                acc[n] = fmaf(a.y, w.y, acc[n]);
                acc[n] = fmaf(a.z, w.z, acc[n]);
                acc[n] = fmaf(a.w, w.w, acc[n]);
            }
        }
        for (int n = 0; n < 64; n++)
            g_skip[(n0 + n) * HF + t] = acc[n];
    }
}

// ---- launch 1: kSZ — scalar scores + zero accumulators ----
__global__ void kSZ(const float* __restrict__ ssv, const float* __restrict__ stv) {
    int id = blockIdx.x * 256 + threadIdx.x;
    g_colsum[id] = 0.f;
    if (id < NN) { g_rowsum[id] = 0.f; g_rowsq[id] = 0.f; }
    int h = id >> 12, n = id & 4095;
    const float4* pr = (const float4*)&g_proj[(h * NN + n) * FOUT];
    const float4* a = (const float4*)(ssv + h * FOUT);
    const float4* b = (const float4*)(stv + h * FOUT);
    float s1 = 0.f, s2 = 0.f;
#pragma unroll
    for (int q = 0; q < 16; q++) {
        float4 p = pr[q];
        float4 av = __ldg(&a[q]);
        float4 bv = __ldg(&b[q]);
        s1 += p.x * av.x + p.y * av.y + p.z * av.z + p.w * av.w;
        s2 += p.x * bv.x + p.y * bv.y + p.z * bv.z + p.w * bv.w;
    }
    g_ssrc[id] = s1;
    g_stgt[id] = s2;
}

// ---- launch 2: kM — mask + row stats + col exp-sums + bf16 attn numerator --
__global__ __launch_bounds__(256) void kM(const float* __restrict__ deg,
                                          const float* __restrict__ bond,
                                          const int* __restrict__ cutp) {
    __shared__ float cs[NHEADS][128];
    int t = threadIdx.x;
    int col = t & 127, half = t >> 7;
    int j0 = blockIdx.x * 128, i0 = blockIdx.y * 128;
    float cut = (float)__ldg(cutp);
    float st[NHEADS], acc[NHEADS];
#pragma unroll
    for (int h = 0; h < NHEADS; h++) {
        st[h] = __ldg(&g_stgt[h * NN + j0 + col]);
        acc[h] = 0.f;
    }
    for (int s = 0; s < 64; s++) {
        int gi = i0 + 2 * s + half;
        size_t g = (size_t)gi * NN + j0 + col;
        float d = deg[g], b = bond[g];
        float wdm = d + b;
        float m = (wdm > 0.f) ? wdm : ((b > cut) ? (b + wdm) : NEG_INF_F);
        g_mask[g] = m;
        float s1 = m, s2 = m * m;
#pragma unroll
        for (int off = 16; off; off >>= 1) {
            s1 += __shfl_down_sync(0xffffffffu, s1, off);
            s2 += __shfl_down_sync(0xffffffffu, s2, off);
        }
        if ((t & 31) == 0) {
            atomicAdd(&g_rowsum[gi], s1);
            atomicAdd(&g_rowsq[gi], s2);
        }
#pragma unroll
        for (int h = 0; h < NHEADS; h++) {
            float x = __ldg(&g_ssrc[h * NN + gi]) + st[h];
            float lr = fmaxf(x, 0.2f * x);
            float e = __expf(lr + m);
            acc[h] += e;
            g_attn[(size_t)(h * NN + gi) * NN + j0 + col] = __float2bfloat16(e);
        }
    }
    if (half == 1) {
#pragma unroll
        for (int h = 0; h < NHEADS; h++) cs[h][col] = acc[h];
    }
    __syncthreads();
    if (half == 0) {
#pragma unroll
        for (int h = 0; h < NHEADS; h++)
            atomicAdd(&g_colsum[h * NN + j0 + col], acc[h] + cs[h][col]);
    }
}

// ---- launch 3: kB — g_projB[h][j][f] = bf16(proj / colsum) ----
__global__ void kB() {
    int id = blockIdx.x * 256 + threadIdx.x;   // 0..262143, 4 f per thread
    int hj = id >> 4;                           // 0..16383
    int f = (id & 15) * 4;
    float cvv = __fdividef(1.0f, g_colsum[hj]);
    float4 p = *(const float4*)&g_proj[hj * FOUT + f];
    __nv_bfloat162 b0 = __floats2bfloat162_rn(p.x * cvv, p.y * cvv);
    __nv_bfloat162 b1 = __floats2bfloat162_rn(p.z * cvv, p.w * cvv);
    uint2 pk;
    pk.x = *(uint32_t*)&b0;
    pk.y = *(uint32_t*)&b1;
    *(uint2*)&g_projB[hj * FOUT + f] = pk;
}

// ---- launch 4: kLN — mask layernorm (streaming) ----
__global__ __launch_bounds__(256) void kLN(float* __restrict__ lnp) {
    int i = blockIdx.x;
    int t = threadIdx.x;
    float mu = g_rowsum[i] * (1.0f / NN);
    float var = fmaxf(g_rowsq[i] * (1.0f / NN) - mu * mu, 0.f);
    float is = rsqrtf(var + 1e-5f);
    const float4* src = (const float4*)(g_mask + (size_t)i * NN);
    float4* dst = (float4*)(lnp + (size_t)i * NN);
#pragma unroll
    for (int q = 0; q < 4; q++) {
        int idx = q * 256 + t;
        float4 m = src[idx];
        dst[idx] = make_float4((m.x - mu) * is, (m.y - mu) * is,
                               (m.z - mu) * is, (m.w - mu) * is);
    }
}

// ---- launch 5: kA8 — pure cp.async + mma.sync GEMM ----
// grid (4h, 16it, 8js) = 512 CTAs, 256 thr. Tile 256i x 64f, K 512j, 16 chunks.
// smem: at bf16 2 bufs (256 rows x 64B, pitch 80) | bst bf16 2 bufs (32 x 128B, pitch 144)
#define AT_OFF   0
#define AT_SZ    20480
#define BST_OFF  40960
#define BST_SZ   4608
#define SMEM_TOT 50176
__global__ __launch_bounds__(256) void kA8() {
    extern __shared__ char dsm[];
    uint32_t at_u  = smem_u32(dsm + AT_OFF);
    uint32_t bst_u = smem_u32(dsm + BST_OFF);

    int t = threadIdx.x;
    int h = blockIdx.x;
    int i0 = blockIdx.y * 256;
    int jbase = blockIdx.z * 512;

    int brow = t >> 3, bseg = t & 7;    // b stage: row 0..31, 16B seg 0..7
    const __nv_bfloat16* abase = g_attn + (size_t)(h * NN + i0 + t) * NN;
    const __nv_bfloat16* bbase = g_projB + (size_t)h * NN * FOUT;

    // prologue: stage chunk 0
    {
        const __nv_bfloat16* asrc = abase + jbase;
        uint32_t adst = at_u + t * 80;
#pragma unroll
        for (int q = 0; q < 4; q++) cp128(adst + q * 16, asrc + q * 8);
        cp128(bst_u + brow * 144 + bseg * 16,
              bbase + (size_t)(jbase + brow) * FOUT + bseg * 8);
        CP_COMMIT();
    }

    int w = t >> 5, l = t & 31;
    float acc0[8][4], acc1[8][4];
#pragma unroll
    for (int n = 0; n < 8; n++)
#pragma unroll
        for (int q = 0; q < 4; q++) { acc0[n][q] = 0.f; acc1[n][q] = 0.f; }

    uint32_t a_frag = at_u + (w * 32 + (l & 15)) * 80 + (l >> 4) * 16;
    uint32_t b_frag = bst_u + (l & 15) * 144 + (l >> 4) * 16;

    for (int c = 0; c < 16; c++) {
        int buf = c & 1;
        CP_WAIT(0);
        __syncthreads();
        // stage chunk c+1 into buf^1 (wrap at end; harmless refetch)
        {
            int j0n = jbase + ((c + 1) & 15) * 32;
            const __nv_bfloat16* asrc = abase + j0n;
            uint32_t adst = at_u + (buf ^ 1) * AT_SZ + t * 80;
#pragma unroll
            for (int q = 0; q < 4; q++) cp128(adst + q * 16, asrc + q * 8);
            cp128(bst_u + (buf ^ 1) * BST_SZ + brow * 144 + bseg * 16,
                  bbase + (size_t)(j0n + brow) * FOUT + bseg * 8);
            CP_COMMIT();
        }
        // GEMM on buf
        uint32_t ab = a_frag + buf * AT_SZ;
        uint32_t bb = b_frag + buf * BST_SZ;
#pragma unroll
        for (int ks = 0; ks < 2; ks++) {
            uint32_t A0[4], A1[4];
            LDSM4(A0, ab + ks * 32);
            LDSM4(A1, ab + ks * 32 + 16 * 80);
#pragma unroll
            for (int nb = 0; nb < 4; nb++) {
                uint32_t B[4];
                LDSM4T(B, bb + ks * 2304 + nb * 32);
                MMA16816(acc0[2 * nb],     A0, B[0], B[1]);
                MMA16816(acc0[2 * nb + 1], A0, B[2], B[3]);
                MMA16816(acc1[2 * nb],     A1, B[0], B[1]);
                MMA16816(acc1[2 * nb + 1], A1, B[2], B[3]);
            }
        }
    }
    // epilogue: write partials
    float* pbase = g_part + ((size_t)(blockIdx.z * NHEADS + h)) * (NN * FOUT);
    int g = l >> 2, tg = l & 3;
#pragma unroll
    for (int mi = 0; mi < 2; mi++) {
        float(*am)[4] = mi ? acc1 : acc0;
        int row0 = i0 + w * 32 + mi * 16 + g;
#pragma unroll
        for (int nf = 0; nf < 8; nf++) {
            int f = nf * 8 + tg * 2;
            *(float2*)&pbase[(size_t)row0 * FOUT + f] =
                make_float2(am[nf][0], am[nf][1]);
            *(float2*)&pbase[(size_t)(row0 + 8) * FOUT + f] =
                make_float2(am[nf][2], am[nf][3]);
        }
    }
}

// ---- launch 6: kC — combine 8 partials + skip + ELU ----
__global__ void kC(float* __restrict__ outp) {
    int id = blockIdx.x * 256 + threadIdx.x;
    int nf = id * 4;
    int n = nf >> 8;
    int c = nf & 255;
    int h = c >> 6, f = c & 63;
    size_t base = ((size_t)h * NN + n) * FOUT + f;
    const size_t stride = (size_t)NHEADS * NN * FOUT;
    float v0 = 0.f, v1 = 0.f, v2 = 0.f, v3 = 0.f;
#pragma unroll
    for (int p = 0; p < 8; p++) {
        float4 pv = *(const float4*)&g_part[base + p * stride];
        v0 += pv.x; v1 += pv.y; v2 += pv.z; v3 += pv.w;
    }
    float4 sk = *(const float4*)&g_skip[n * HF + c];
    v0 += sk.x; v1 += sk.y; v2 += sk.z; v3 += sk.w;
    v0 = v0 > 0.f ? v0 : expm1f(v0);
    v1 = v1 > 0.f ? v1 : expm1f(v1);
    v2 = v2 > 0.f ? v2 : expm1f(v2);
    v3 = v3 > 0.f ? v3 : expm1f(v3);
    *(float4*)&outp[nf] = make_float4(v0, v1, v2, v3);
}

// ---------------- host launch ----------------
extern "C" void kernel_launch(void* const* d_in, const int* in_sizes, int n_in,
                              void* d_out, int out_size) {
    const float* nodes = (const float*)d_in[0];
    const float* deg   = (const float*)d_in[1];
    const float* bond  = (const float*)d_in[3];
    const float* pp    = (const float*)d_in[4];
    const float* ssv   = (const float*)d_in[5];
    const float* stv   = (const float*)d_in[6];
    const float* sw    = (const float*)d_in[7];
    const int*   cutp  = (const int*)d_in[8];

    float* outp = (float*)d_out;            // [4096, 256]
    float* lnp  = outp + NN * HF;           // [4096, 4096]

    cudaFuncSetAttribute(kA8, cudaFuncAttributeMaxDynamicSharedMemorySize,
                         SMEM_TOT);

    kP2<<<dim3(2, 64), 256>>>(nodes, pp, sw);
    kSZ<<<64, 256>>>(ssv, stv);
    kM<<<dim3(32, 32), 256>>>(deg, bond, cutp);
    kB<<<1024, 256>>>();
    kLN<<<4096, 256>>>(lnp);
    kA8<<<dim3(4, 16, 8), 256, SMEM_TOT>>>();
    kC<<<1024, 256>>>(outp);
}